// round 12
// baseline (speedup 1.0000x reference)
#include <cuda_runtime.h>
#include <math.h>

#define NP 2048
#define NN 4096
#define DX 768
#define DY 512
#define DF 256
#define SPLITK 8

// ------------------------------------------------------------------
// device scratch (static globals; no allocation)
// ------------------------------------------------------------------
__device__ float g_Xa[NN*DX];
__device__ float g_Ya[NN*DY];
__device__ float g_Sxx[DX*DX];
__device__ float g_Syy[DY*DY];
__device__ float g_Sxy[DX*DY];
__device__ float g_fXp[NP*DF], g_fYp[NP*DF];
__device__ float g_fXn[NN*DF], g_fYn[NN*DF];
__device__ float g_Mp[(size_t)NP*NP];
__device__ float g_Mu[(size_t)NN*NN];
__device__ float g_Ma[(size_t)NN*NN];
__device__ float g_Pu[(size_t)NN*NN];
__device__ float g_Xn[NN*DX], g_Yn[NN*DY];
__device__ float g_Xu[NN*DX], g_Yu[NN*DY];
__device__ float g_T1[NN*DX];
__device__ float g_PY[NN*DY];
__device__ float g_Gxx[DX*DX], g_Gyy[DY*DY];
__device__ float g_Cf[DF*DF], g_Dff[DF*DF];
__device__ float g_XF[DX*DF], g_FY[DF*DY];
__device__ float g_Axx[DX*DX], g_Ayy[DY*DY];
__device__ float g_W[DX*DY];
__device__ float g_Ta[DX*DY], g_Tb[DX*DY];
__device__ float g_slab[SPLITK*DX*DX];
__device__ float g_uu[NN], g_vu[NN], g_ua[NN], g_va[NN], g_up[NP], g_vp[NP];
__device__ float g_ps[32*NN];
__device__ float g_av[NN], g_bv[NN], g_rsp[NP], g_csp[NP];
__device__ float g_prow[NN], g_dexp[NP], g_dimp[NP], g_potr[NN];
__device__ float g_S[16];

// ------------------------------------------------------------------
// helpers
// ------------------------------------------------------------------
__device__ __forceinline__ float fexp(float x) {
    // FMA-pipe exp: exp(x) = 2^k * e^t, t = x - k*ln2, |t| <= 0.3466
    x = fminf(fmaxf(x, -80.f), 60.f);
    float y  = fmaf(x, 1.4426950408889634f, 12582912.f);
    int   k  = __float_as_int(y) - 0x4B400000;
    float yr = y - 12582912.f;
    float t  = fmaf(yr, -0.693359375f, x);
    t = fmaf(yr, 2.12194440e-4f, t);
    float p = 1.3888889e-3f;
    p = fmaf(p, t, 8.3333333e-3f);
    p = fmaf(p, t, 4.1666667e-2f);
    p = fmaf(p, t, 1.6666667e-1f);
    p = fmaf(p, t, 5.0e-1f);
    p = fmaf(p, t, 1.0f);
    p = fmaf(p, t, 1.0f);
    return p * __int_as_float((k + 127) << 23);
}

__device__ __forceinline__ float blockSum(float v) {
    __shared__ float sh[33];
    int lane = threadIdx.x & 31, w = threadIdx.x >> 5, nw = blockDim.x >> 5;
#pragma unroll
    for (int o = 16; o > 0; o >>= 1) v += __shfl_xor_sync(0xffffffffu, v, o);
    if (lane == 0) sh[w] = v;
    __syncthreads();
    if (w == 0) {
        float r = (lane < nw) ? sh[lane] : 0.f;
#pragma unroll
        for (int o = 16; o > 0; o >>= 1) r += __shfl_xor_sync(0xffffffffu, r, o);
        if (lane == 0) sh[32] = r;
    }
    __syncthreads();
    float r = sh[32];
    __syncthreads();
    return r;
}

// ------------------------------------------------------------------
// elementwise / row kernels
// ------------------------------------------------------------------
__global__ void rownorm_k(const float* __restrict__ in, float* __restrict__ out, int d) {
    int row = blockIdx.x;
    const float* r = in + (size_t)row * d;
    float s = 0.f;
    for (int j = threadIdx.x; j < d; j += blockDim.x) { float x = r[j]; s += x * x; }
    s = blockSum(s);
    float inv = 1.f / fmaxf(sqrtf(s), 1e-8f);
    float* o = out + (size_t)row * d;
    for (int j = threadIdx.x; j < d; j += blockDim.x) o[j] = r[j] * inv;
}

__global__ void rowdot_scale_k(const float* __restrict__ Xin, const float* __restrict__ XS,
                               float* __restrict__ out, int d) {
    int row = blockIdx.x;
    const float* r = Xin + (size_t)row * d;
    const float* q = XS + (size_t)row * d;
    float s = 0.f;
    for (int j = threadIdx.x; j < d; j += blockDim.x) s += r[j] * q[j];
    s = blockSum(s);
    float inv = 1.f / fmaxf(sqrtf(s), 1e-8f);
    float* o = out + (size_t)row * d;
    for (int j = threadIdx.x; j < d; j += blockDim.x) o[j] = r[j] * inv;
}

// ------------------------------------------------------------------
// generic 64x64x16 SGEMM. OPA=0: A is MxK; OPA=1: A is KxM (computes A^T B).
// OPB=0: B is KxN; OPB=1: B is NxK. SCALEK: scale A's k-rows by wk[k] (OPA=1 only).
// gridDim.z = S > 1: each z writes a raw slab C[z*M*N + ...]; alpha applied in reduce.
// ------------------------------------------------------------------
template<int OPA, int OPB, int SCALEK>
__global__ void __launch_bounds__(256, 2) gemm64(
    const float* __restrict__ A, const float* __restrict__ B, float* __restrict__ C,
    int M, int N, int K, float alpha, const float* __restrict__ wk)
{
    __shared__ __align__(16) float As[16][64];
    __shared__ __align__(16) float Bs[16][64];
    const int tid = threadIdx.x;
    const int m0 = blockIdx.y * 64, n0 = blockIdx.x * 64;
    const int S = gridDim.z;
    const int klen = K / S;
    const int kbeg = blockIdx.z * klen;
    const int tx = tid & 15, ty = tid >> 4;

    float acc[4][4];
#pragma unroll
    for (int i = 0; i < 4; i++)
#pragma unroll
        for (int j = 0; j < 4; j++) acc[i][j] = 0.f;

    for (int k0 = kbeg; k0 < kbeg + klen; k0 += 16) {
        if (OPA == 1) {
            int m4 = (tid & 15) << 2, k = tid >> 4;
            float4 va = *(const float4*)(A + (size_t)(k0 + k) * M + m0 + m4);
            if (SCALEK) { float w = wk[k0 + k]; va.x *= w; va.y *= w; va.z *= w; va.w *= w; }
            *(float4*)&As[k][m4] = va;
        } else {
            int m = tid >> 2, k4 = (tid & 3) << 2;
            float4 va = *(const float4*)(A + (size_t)(m0 + m) * K + k0 + k4);
            As[k4 + 0][m] = va.x; As[k4 + 1][m] = va.y; As[k4 + 2][m] = va.z; As[k4 + 3][m] = va.w;
        }
        if (OPB == 0) {
            int n4 = (tid & 15) << 2, k = tid >> 4;
            *(float4*)&Bs[k][n4] = *(const float4*)(B + (size_t)(k0 + k) * N + n0 + n4);
        } else {
            int n = tid >> 2, k4 = (tid & 3) << 2;
            float4 vb = *(const float4*)(B + (size_t)(n0 + n) * K + k0 + k4);
            Bs[k4 + 0][n] = vb.x; Bs[k4 + 1][n] = vb.y; Bs[k4 + 2][n] = vb.z; Bs[k4 + 3][n] = vb.w;
        }
        __syncthreads();
#pragma unroll
        for (int kk = 0; kk < 16; kk++) {
            float4 a4 = *(const float4*)&As[kk][ty << 2];
            float4 b4 = *(const float4*)&Bs[kk][tx << 2];
            float a[4] = { a4.x, a4.y, a4.z, a4.w };
            float b[4] = { b4.x, b4.y, b4.z, b4.w };
#pragma unroll
            for (int i = 0; i < 4; i++)
#pragma unroll
                for (int j = 0; j < 4; j++) acc[i][j] = fmaf(a[i], b[j], acc[i][j]);
        }
        __syncthreads();
    }

    float* Co = (S > 1) ? (C + (size_t)blockIdx.z * M * N) : C;
    float sc = (S > 1) ? 1.f : alpha;
#pragma unroll
    for (int i = 0; i < 4; i++) {
        float4 o = make_float4(acc[i][0] * sc, acc[i][1] * sc, acc[i][2] * sc, acc[i][3] * sc);
        *(float4*)(Co + (size_t)(m0 + (ty << 2) + i) * N + n0 + (tx << 2)) = o;
    }
}

__global__ void reduce_slabs_k(const float* __restrict__ src, float* __restrict__ dst,
                               int S, int MN, float alpha) {
    int idx = blockIdx.x * blockDim.x + threadIdx.x;
    if (idx >= MN) return;
    float s = 0.f;
    for (int z = 0; z < S; z++) s += src[(size_t)z * MN + idx];
    dst[idx] = s * alpha;
}

// ------------------------------------------------------------------
// sinkhorn (no-max LSE; args bounded) + marginal passes
// ------------------------------------------------------------------
__global__ void sinkrow_k(const float* __restrict__ Mm, const float* __restrict__ v,
                          float* __restrict__ u, int ncols, float log_a) {
    int row = blockIdx.x;
    const float* Mr = Mm + (size_t)row * ncols;
    float s = 0.f;
    for (int j = threadIdx.x; j < ncols; j += blockDim.x) s += fexp(Mr[j] + v[j]);
    s = blockSum(s);
    if (threadIdx.x == 0) u[row] = log_a - logf(s);
}

__global__ void colpartexp_k(const float* __restrict__ Mm, const float* __restrict__ u,
                             float* __restrict__ ps, int ncols, int chunk) {
    int col = blockIdx.x * blockDim.x + threadIdx.x;
    int r0 = blockIdx.y * chunk;
    float s = 0.f;
    for (int r = r0; r < r0 + chunk; r++) s += fexp(Mm[(size_t)r * ncols + col] + u[r]);
    ps[(size_t)blockIdx.y * ncols + col] = s;
}

__global__ void colcombsink_k(const float* __restrict__ ps, float* __restrict__ v,
                              int nch, int ncols, float log_b) {
    int col = blockIdx.x * blockDim.x + threadIdx.x;
    float s = 0.f;
    for (int c = 0; c < nch; c++) s += ps[(size_t)c * ncols + col];
    v[col] = log_b - logf(s);
}

__global__ void colcombmarg_k(const float* __restrict__ ps, const float* __restrict__ v,
                              float* __restrict__ cs, int nch, int ncols) {
    int col = blockIdx.x * blockDim.x + threadIdx.x;
    float s = 0.f;
    for (int c = 0; c < nch; c++) s += ps[(size_t)c * ncols + col];
    cs[col] = s * fexp(v[col]);
}

__global__ void rowsumexp_k(const float* __restrict__ Mm, const float* __restrict__ u,
                            const float* __restrict__ v, float* __restrict__ rs, int ncols) {
    int row = blockIdx.x;
    const float* Mr = Mm + (size_t)row * ncols;
    float s = 0.f;
    for (int j = threadIdx.x; j < ncols; j += blockDim.x) s += fexp(Mr[j] + v[j]);
    s = blockSum(s);
    if (threadIdx.x == 0) rs[row] = s * fexp(u[row]);
}

__global__ void expplan_k(const float* __restrict__ Mm, const float* __restrict__ u,
                          const float* __restrict__ v, float* __restrict__ P) {
    size_t idx = (size_t)blockIdx.x * blockDim.x + threadIdx.x;
    int i = (int)(idx >> 12), j = (int)(idx & 4095);
    P[idx] = fexp(Mm[idx] + u[i] + v[j]);
}

__global__ void rowsumplain_k(const float* __restrict__ P, float* __restrict__ rs, int ncols) {
    int row = blockIdx.x;
    const float* Pr = P + (size_t)row * ncols;
    float s = 0.f;
    for (int j = threadIdx.x; j < ncols; j += blockDim.x) s += Pr[j];
    s = blockSum(s);
    if (threadIdx.x == 0) rs[row] = s;
}

__global__ void colpartplain_k(const float* __restrict__ P, float* __restrict__ ps,
                               int ncols, int chunk) {
    int col = blockIdx.x * blockDim.x + threadIdx.x;
    int r0 = blockIdx.y * chunk;
    float s = 0.f;
    for (int r = r0; r < r0 + chunk; r++) s += P[(size_t)r * ncols + col];
    ps[(size_t)blockIdx.y * ncols + col] = s;
}

__global__ void colcombplain_k(const float* __restrict__ ps, float* __restrict__ cs,
                               int nch, int ncols) {
    int col = blockIdx.x * blockDim.x + threadIdx.x;
    float s = 0.f;
    for (int c = 0; c < nch; c++) s += ps[(size_t)c * ncols + col];
    cs[col] = s;
}

// ------------------------------------------------------------------
// loss passes
// ------------------------------------------------------------------
__global__ void sail_k(const float* __restrict__ Mp, const float* __restrict__ u,
                       const float* __restrict__ v, float* __restrict__ prow,
                       float* __restrict__ dexp, float* __restrict__ dimp) {
    int row = blockIdx.x;
    const float* Mr = Mp + (size_t)row * NP;
    float acc = 0.f;
    for (int j = threadIdx.x; j < NP; j += blockDim.x) {
        float m = Mr[j];
        float z = (j == row) ? (m * 0.5f) : (-m * 0.5f);   // cos*10*target, cos = m/20
        float ls = (z >= 0.f) ? -log1pf(fexp(-z)) : (z - log1pf(fexp(z)));
        acc += ls;
        if (j == row) {
            dexp[row] = (1.f - m * 0.05f) * 0.5f;
            dimp[row] = m + u[row] + v[row];
        }
    }
    acc = blockSum(acc);
    if (threadIdx.x == 0) prow[row] = acc;
}

__global__ void ot_k(const float* __restrict__ Ma, const float* __restrict__ ua,
                     const float* __restrict__ va, const float* __restrict__ Mu,
                     const float* __restrict__ uu, const float* __restrict__ vu,
                     float* __restrict__ prow) {
    int row = blockIdx.x;
    size_t off = (size_t)row * NN;
    float uai = ua[row], uui = uu[row];
    float acc = 0.f;
    for (int j = threadIdx.x; j < NN; j += blockDim.x) {
        float ta = Ma[off + j] + uai + va[j];
        float tu = Mu[off + j] + uui + vu[j];
        acc += fexp(ta) * (ta - tu);
    }
    acc = blockSum(acc);
    if (threadIdx.x == 0) prow[row] = acc;
}

// ------------------------------------------------------------------
// scalar reductions (single block, 1024 threads)
// ------------------------------------------------------------------
__global__ void rsum_k(const float* __restrict__ a, int n, float* __restrict__ dst) {
    float s = 0.f;
    for (int i = threadIdx.x; i < n; i += blockDim.x) s += a[i];
    s = blockSum(s);
    if (threadIdx.x == 0) *dst = s;
}
__global__ void rdot_k(const float* __restrict__ a, const float* __restrict__ b,
                       int n, float* __restrict__ dst) {
    float s = 0.f;
    for (int i = threadIdx.x; i < n; i += blockDim.x) s = fmaf(a[i], b[i], s);
    s = blockSum(s);
    if (threadIdx.x == 0) *dst = s;
}
__global__ void rsqdev_k(const float* __restrict__ a, int n, float c, float* __restrict__ dst) {
    float s = 0.f;
    for (int i = threadIdx.x; i < n; i += blockDim.x) { float d = a[i] - c; s = fmaf(d, d, s); }
    s = blockSum(s);
    if (threadIdx.x == 0) *dst = s;
}

__global__ void final_k(const float* __restrict__ S, float* __restrict__ out) {
    float L_marg = S[0] + S[1] + S[2] + S[3];
    float L_sail = -S[4] / (2048.f * 2048.f);
    float L_exp  = S[5] / 2048.f;
    float L_imp  = -(S[6] / 2048.f + logf(2048.f));
    float L_ot   = S[7];
    float L_div  = (S[8] + S[9] - 2.f * S[10]) / (4096.f * 4096.f);
    float L_gw   = S[11] + S[12] - 2.f * S[13];
    out[0] = L_marg + L_sail + L_exp + L_imp + L_ot + L_div + L_gw;
}

// ------------------------------------------------------------------
// host
// ------------------------------------------------------------------
static float* gp(const void* sym) {
    void* p = nullptr;
    cudaGetSymbolAddress(&p, sym);
    return (float*)p;
}

extern "C" void kernel_launch(void* const* d_in, const int* in_sizes, int n_in,
                              void* d_out, int out_size) {
    (void)in_sizes; (void)n_in; (void)out_size;
    const float* pfXp = (const float*)d_in[0];
    const float* pfYp = (const float*)d_in[1];
    const float* pX   = (const float*)d_in[2];
    const float* pY   = (const float*)d_in[3];
    const float* pfX  = (const float*)d_in[4];
    const float* pfY  = (const float*)d_in[5];
    const float* pXaI = (const float*)d_in[6];
    const float* pYaI = (const float*)d_in[7];

    float *pXa = gp(g_Xa), *pYa = gp(g_Ya);
    float *pSxx = gp(g_Sxx), *pSyy = gp(g_Syy), *pSxy = gp(g_Sxy);
    float *pfXpn = gp(g_fXp), *pfYpn = gp(g_fYp);
    float *pfXn = gp(g_fXn), *pfYn = gp(g_fYn);
    float *pMp = gp(g_Mp), *pMu = gp(g_Mu), *pMa = gp(g_Ma), *pPu = gp(g_Pu);
    float *pXn = gp(g_Xn), *pYn = gp(g_Yn), *pXu = gp(g_Xu), *pYu = gp(g_Yu);
    float *pT1 = gp(g_T1), *pPY = gp(g_PY);
    float *pGxx = gp(g_Gxx), *pGyy = gp(g_Gyy);
    float *pCf = gp(g_Cf), *pDff = gp(g_Dff);
    float *pXF = gp(g_XF), *pFY = gp(g_FY);
    float *pAxx = gp(g_Axx), *pAyy = gp(g_Ayy), *pW = gp(g_W);
    float *pTa = gp(g_Ta), *pTb = gp(g_Tb), *pSlab = gp(g_slab);
    float *puu = gp(g_uu), *pvu = gp(g_vu), *pua = gp(g_ua), *pva = gp(g_va);
    float *pup = gp(g_up), *pvp = gp(g_vp), *pps = gp(g_ps);
    float *pav = gp(g_av), *pbv = gp(g_bv), *prsp = gp(g_rsp), *pcsp = gp(g_csp);
    float *pprow = gp(g_prow), *pdexp = gp(g_dexp), *pdimp = gp(g_dimp), *ppotr = gp(g_potr);
    float *pS = gp(g_S);

    const float logN4 = -logf((float)NN);
    const float logN2 = -logf((float)NP);

    // --- row normalizations ---
    rownorm_k<<<NN, 256>>>(pXaI, pXa, DX);
    rownorm_k<<<NN, 256>>>(pYaI, pYa, DY);
    rownorm_k<<<NP, 256>>>(pfXp, pfXpn, DF);
    rownorm_k<<<NP, 256>>>(pfYp, pfYpn, DF);
    rownorm_k<<<NN, 256>>>(pfX, pfXn, DF);
    rownorm_k<<<NN, 256>>>(pfY, pfYn, DF);
    rownorm_k<<<NN, 256>>>(pX, pXu, DX);
    rownorm_k<<<NN, 256>>>(pY, pYu, DY);

    // --- anchor covariances (TN, split-K slabs) ---
    gemm64<1,0,0><<<dim3(DX/64, DX/64, SPLITK), 256>>>(pXa, pXa, pSlab, DX, DX, NN, 1.f, nullptr);
    reduce_slabs_k<<<(DX*DX+255)/256, 256>>>(pSlab, pSxx, SPLITK, DX*DX, 1.f/NN);
    gemm64<1,0,0><<<dim3(DY/64, DY/64, SPLITK), 256>>>(pYa, pYa, pSlab, DY, DY, NN, 1.f, nullptr);
    reduce_slabs_k<<<(DY*DY+255)/256, 256>>>(pSlab, pSyy, SPLITK, DY*DY, 1.f/NN);
    gemm64<1,0,0><<<dim3(DY/64, DX/64, SPLITK), 256>>>(pXa, pYa, pSlab, DX, DY, NN, 1.f, nullptr);
    reduce_slabs_k<<<(DX*DY+255)/256, 256>>>(pSlab, pSxy, SPLITK, DX*DY, 1.f/NN);

    // --- anchored normalizations Xn, Yn ---
    gemm64<0,0,0><<<dim3(DX/64, NN/64), 256>>>(pX, pSxx, pT1, NN, DX, DX, 1.f, nullptr);
    rowdot_scale_k<<<NN, 256>>>(pX, pT1, pXn, DX);
    gemm64<0,0,0><<<dim3(DY/64, NN/64), 256>>>(pY, pSyy, pT1, NN, DY, DY, 1.f, nullptr);
    rowdot_scale_k<<<NN, 256>>>(pY, pT1, pYn, DY);

    // --- cost matrices (M = sim * 20) ---
    gemm64<0,0,0><<<dim3(DY/64, NN/64), 256>>>(pXn, pSxy, pT1, NN, DY, DX, 1.f, nullptr);
    gemm64<0,1,0><<<dim3(NN/64, NN/64), 256>>>(pT1, pYn, pMa, NN, NN, DY, 20.f, nullptr);
    gemm64<0,1,0><<<dim3(NN/64, NN/64), 256>>>(pfXn, pfYn, pMu, NN, NN, DF, 20.f, nullptr);
    gemm64<0,1,0><<<dim3(NP/64, NP/64), 256>>>(pfXpn, pfYpn, pMp, NP, NP, DF, 20.f, nullptr);

    // --- sinkhorn: plan_u on Mu ---
    cudaMemsetAsync(puu, 0, NN*sizeof(float));
    cudaMemsetAsync(pvu, 0, NN*sizeof(float));
    for (int it = 0; it < 10; ++it) {
        sinkrow_k<<<NN, 256>>>(pMu, pvu, puu, NN, logN4);
        colpartexp_k<<<dim3(NN/256, 32), 256>>>(pMu, puu, pps, NN, 128);
        colcombsink_k<<<NN/256, 256>>>(pps, pvu, 32, NN, logN4);
    }
    // --- sinkhorn: plan_a on Ma ---
    cudaMemsetAsync(pua, 0, NN*sizeof(float));
    cudaMemsetAsync(pva, 0, NN*sizeof(float));
    for (int it = 0; it < 10; ++it) {
        sinkrow_k<<<NN, 256>>>(pMa, pva, pua, NN, logN4);
        colpartexp_k<<<dim3(NN/256, 32), 256>>>(pMa, pua, pps, NN, 128);
        colcombsink_k<<<NN/256, 256>>>(pps, pva, 32, NN, logN4);
    }
    // --- sinkhorn: plan_p on Mp ---
    cudaMemsetAsync(pup, 0, NP*sizeof(float));
    cudaMemsetAsync(pvp, 0, NP*sizeof(float));
    for (int it = 0; it < 10; ++it) {
        sinkrow_k<<<NP, 256>>>(pMp, pvp, pup, NP, logN2);
        colpartexp_k<<<dim3(NP/256, 16), 256>>>(pMp, pup, pps, NP, 128);
        colcombsink_k<<<NP/256, 256>>>(pps, pvp, 16, NP, logN2);
    }

    // --- plan_u materialize + marginals a, b ---
    expplan_k<<<(unsigned)((size_t)NN*NN/1024), 1024>>>(pMu, puu, pvu, pPu);
    rowsumplain_k<<<NN, 256>>>(pPu, pav, NN);
    colpartplain_k<<<dim3(NN/256, 32), 256>>>(pPu, pps, NN, 128);
    colcombplain_k<<<NN/256, 256>>>(pps, pbv, 32, NN);
    rsqdev_k<<<1, 1024>>>(pav, NN, 1.f/NN, pS + 2);
    rsqdev_k<<<1, 1024>>>(pbv, NN, 1.f/NN, pS + 3);

    // --- plan_p marginals ---
    rowsumexp_k<<<NP, 256>>>(pMp, pup, pvp, prsp, NP);
    colpartexp_k<<<dim3(NP/256, 16), 256>>>(pMp, pup, pps, NP, 128);
    colcombmarg_k<<<NP/256, 256>>>(pps, pvp, pcsp, 16, NP);
    rsqdev_k<<<1, 1024>>>(prsp, NP, 1.f/NP, pS + 0);
    rsqdev_k<<<1, 1024>>>(pcsp, NP, 1.f/NP, pS + 1);

    // --- sail / exp / imp ---
    sail_k<<<NP, 256>>>(pMp, pup, pvp, pprow, pdexp, pdimp);
    rsum_k<<<1, 1024>>>(pprow, NP, pS + 4);
    rsum_k<<<1, 1024>>>(pdexp, NP, pS + 5);
    rsum_k<<<1, 1024>>>(pdimp, NP, pS + 6);

    // --- OT KL term ---
    ot_k<<<NN, 256>>>(pMa, pua, pva, pMu, puu, pvu, ppotr);
    rsum_k<<<1, 1024>>>(ppotr, NN, pS + 7);

    // --- divergence terms ---
    gemm64<1,0,0><<<dim3(DX/64, DX/64, SPLITK), 256>>>(pXn, pXn, pSlab, DX, DX, NN, 1.f, nullptr);
    reduce_slabs_k<<<(DX*DX+255)/256, 256>>>(pSlab, pGxx, SPLITK, DX*DX, 1.f);
    gemm64<1,0,0><<<dim3(DY/64, DY/64, SPLITK), 256>>>(pYn, pYn, pSlab, DY, DY, NN, 1.f, nullptr);
    reduce_slabs_k<<<(DY*DY+255)/256, 256>>>(pSlab, pGyy, SPLITK, DY*DY, 1.f);
    gemm64<1,0,0><<<dim3(DF/64, DF/64, SPLITK), 256>>>(pfXn, pfXn, pSlab, DF, DF, NN, 1.f, nullptr);
    reduce_slabs_k<<<(DF*DF+255)/256, 256>>>(pSlab, pCf, SPLITK, DF*DF, 1.f);
    gemm64<1,0,0><<<dim3(DF/64, DF/64, SPLITK), 256>>>(pfYn, pfYn, pSlab, DF, DF, NN, 1.f, nullptr);
    reduce_slabs_k<<<(DF*DF+255)/256, 256>>>(pSlab, pDff, SPLITK, DF*DF, 1.f);
    gemm64<1,0,0><<<dim3(DF/64, DX/64, SPLITK), 256>>>(pXn, pfXn, pSlab, DX, DF, NN, 1.f, nullptr);
    reduce_slabs_k<<<(DX*DF+255)/256, 256>>>(pSlab, pXF, SPLITK, DX*DF, 1.f);
    gemm64<1,0,0><<<dim3(DY/64, DF/64, SPLITK), 256>>>(pfYn, pYn, pSlab, DF, DY, NN, 1.f, nullptr);
    reduce_slabs_k<<<(DF*DY+255)/256, 256>>>(pSlab, pFY, SPLITK, DF*DY, 1.f);

    gemm64<0,0,0><<<dim3(DY/64, DX/64), 256>>>(pGxx, pSxy, pTa, DX, DY, DX, 1.f, nullptr);
    gemm64<0,0,0><<<dim3(DY/64, DX/64), 256>>>(pTa, pGyy, pTb, DX, DY, DY, 1.f, nullptr);
    rdot_k<<<1, 1024>>>(pTb, pSxy, DX*DY, pS + 8);
    rdot_k<<<1, 1024>>>(pCf, pDff, DF*DF, pS + 9);
    gemm64<0,0,0><<<dim3(DY/64, DX/64), 256>>>(pXF, pFY, pTa, DX, DY, DF, 1.f, nullptr);
    rdot_k<<<1, 1024>>>(pTa, pSxy, DX*DY, pS + 10);

    // --- GW terms ---
    gemm64<1,0,1><<<dim3(DX/64, DX/64, SPLITK), 256>>>(pXu, pXu, pSlab, DX, DX, NN, 1.f, pav);
    reduce_slabs_k<<<(DX*DX+255)/256, 256>>>(pSlab, pAxx, SPLITK, DX*DX, 1.f);
    gemm64<1,0,1><<<dim3(DY/64, DY/64, SPLITK), 256>>>(pYu, pYu, pSlab, DY, DY, NN, 1.f, pbv);
    reduce_slabs_k<<<(DY*DY+255)/256, 256>>>(pSlab, pAyy, SPLITK, DY*DY, 1.f);
    rdot_k<<<1, 1024>>>(pAxx, pAxx, DX*DX, pS + 11);
    rdot_k<<<1, 1024>>>(pAyy, pAyy, DY*DY, pS + 12);

    gemm64<0,0,0><<<dim3(DY/64, NN/64), 256>>>(pPu, pYu, pPY, NN, DY, NN, 1.f, nullptr);
    gemm64<1,0,0><<<dim3(DY/64, DX/64, SPLITK), 256>>>(pXu, pPY, pSlab, DX, DY, NN, 1.f, nullptr);
    reduce_slabs_k<<<(DX*DY+255)/256, 256>>>(pSlab, pW, SPLITK, DX*DY, 1.f);
    rdot_k<<<1, 1024>>>(pW, pW, DX*DY, pS + 13);

    // --- combine ---
    final_k<<<1, 1>>>(pS, (float*)d_out);
}

// round 16
// speedup vs baseline: 1.0001x; 1.0001x over previous
#include <cuda_runtime.h>
#include <math.h>

#define NP 2048
#define NN 4096
#define DX 768
#define DY 512
#define DF 256
#define SPLITK 8

// ------------------------------------------------------------------
// device scratch (static globals; no allocation)
// ------------------------------------------------------------------
__device__ float g_Xa[NN*DX];
__device__ float g_Ya[NN*DY];
__device__ float g_Sxx[DX*DX];
__device__ float g_Syy[DY*DY];
__device__ float g_Sxy[DX*DY];
__device__ float g_fXp[NP*DF], g_fYp[NP*DF];
__device__ float g_fXn[NN*DF], g_fYn[NN*DF];
__device__ float g_Mp[(size_t)NP*NP];
__device__ float g_Mu[(size_t)NN*NN];
__device__ float g_Ma[(size_t)NN*NN];
__device__ float g_Pu[(size_t)NN*NN];
__device__ float g_Xn[NN*DX], g_Yn[NN*DY];
__device__ float g_Xu[NN*DX], g_Yu[NN*DY];
__device__ float g_T1[NN*DX];
__device__ float g_PY[NN*DY];
__device__ float g_Gxx[DX*DX], g_Gyy[DY*DY];
__device__ float g_Cf[DF*DF], g_Dff[DF*DF];
__device__ float g_XF[DX*DF], g_FY[DF*DY];
__device__ float g_Axx[DX*DX], g_Ayy[DY*DY];
__device__ float g_W[DX*DY];
__device__ float g_Ta[DX*DY], g_Tb[DX*DY];
__device__ float g_slab[SPLITK*DX*DX];
__device__ float g_uu[NN], g_vu[NN], g_ua[NN], g_va[NN], g_up[NP], g_vp[NP];
__device__ float g_ps[32*NN];
__device__ float g_av[NN], g_bv[NN], g_rsp[NP], g_csp[NP];
__device__ float g_prow[NN], g_dexp[NP], g_dimp[NP], g_potr[NN];
__device__ float g_S[16];

// ------------------------------------------------------------------
// helpers
// ------------------------------------------------------------------
__device__ __forceinline__ float fexp(float x) {
    // FMA-pipe exp: exp(x) = 2^k * e^t, t = x - k*ln2, |t| <= 0.3466
    x = fminf(fmaxf(x, -80.f), 60.f);
    float y  = fmaf(x, 1.4426950408889634f, 12582912.f);
    int   k  = __float_as_int(y) - 0x4B400000;
    float yr = y - 12582912.f;
    float t  = fmaf(yr, -0.693359375f, x);
    t = fmaf(yr, 2.12194440e-4f, t);
    float p = 1.3888889e-3f;
    p = fmaf(p, t, 8.3333333e-3f);
    p = fmaf(p, t, 4.1666667e-2f);
    p = fmaf(p, t, 1.6666667e-1f);
    p = fmaf(p, t, 5.0e-1f);
    p = fmaf(p, t, 1.0f);
    p = fmaf(p, t, 1.0f);
    return p * __int_as_float((k + 127) << 23);
}

__device__ __forceinline__ float blockSum(float v) {
    __shared__ float sh[33];
    int lane = threadIdx.x & 31, w = threadIdx.x >> 5, nw = blockDim.x >> 5;
#pragma unroll
    for (int o = 16; o > 0; o >>= 1) v += __shfl_xor_sync(0xffffffffu, v, o);
    if (lane == 0) sh[w] = v;
    __syncthreads();
    if (w == 0) {
        float r = (lane < nw) ? sh[lane] : 0.f;
#pragma unroll
        for (int o = 16; o > 0; o >>= 1) r += __shfl_xor_sync(0xffffffffu, r, o);
        if (lane == 0) sh[32] = r;
    }
    __syncthreads();
    float r = sh[32];
    __syncthreads();
    return r;
}

// ------------------------------------------------------------------
// elementwise / row kernels
// ------------------------------------------------------------------
__global__ void rownorm_k(const float* __restrict__ in, float* __restrict__ out, int d) {
    int row = blockIdx.x;
    const float* r = in + (size_t)row * d;
    float s = 0.f;
    for (int j = threadIdx.x; j < d; j += blockDim.x) { float x = r[j]; s += x * x; }
    s = blockSum(s);
    float inv = 1.f / fmaxf(sqrtf(s), 1e-8f);
    float* o = out + (size_t)row * d;
    for (int j = threadIdx.x; j < d; j += blockDim.x) o[j] = r[j] * inv;
}

__global__ void rowdot_scale_k(const float* __restrict__ Xin, const float* __restrict__ XS,
                               float* __restrict__ out, int d) {
    int row = blockIdx.x;
    const float* r = Xin + (size_t)row * d;
    const float* q = XS + (size_t)row * d;
    float s = 0.f;
    for (int j = threadIdx.x; j < d; j += blockDim.x) s += r[j] * q[j];
    s = blockSum(s);
    float inv = 1.f / fmaxf(sqrtf(s), 1e-8f);
    float* o = out + (size_t)row * d;
    for (int j = threadIdx.x; j < d; j += blockDim.x) o[j] = r[j] * inv;
}

// ------------------------------------------------------------------
// generic 64x64x16 SGEMM. OPA=0: A is MxK; OPA=1: A is KxM (computes A^T B).
// OPB=0: B is KxN; OPB=1: B is NxK. SCALEK: scale A's k-rows by wk[k] (OPA=1 only).
// gridDim.z = S > 1: each z writes a raw slab C[z*M*N + ...]; alpha applied in reduce.
// ------------------------------------------------------------------
template<int OPA, int OPB, int SCALEK>
__global__ void __launch_bounds__(256, 2) gemm64(
    const float* __restrict__ A, const float* __restrict__ B, float* __restrict__ C,
    int M, int N, int K, float alpha, const float* __restrict__ wk)
{
    __shared__ __align__(16) float As[16][64];
    __shared__ __align__(16) float Bs[16][64];
    const int tid = threadIdx.x;
    const int m0 = blockIdx.y * 64, n0 = blockIdx.x * 64;
    const int S = gridDim.z;
    const int klen = K / S;
    const int kbeg = blockIdx.z * klen;
    const int tx = tid & 15, ty = tid >> 4;

    float acc[4][4];
#pragma unroll
    for (int i = 0; i < 4; i++)
#pragma unroll
        for (int j = 0; j < 4; j++) acc[i][j] = 0.f;

    for (int k0 = kbeg; k0 < kbeg + klen; k0 += 16) {
        if (OPA == 1) {
            int m4 = (tid & 15) << 2, k = tid >> 4;
            float4 va = *(const float4*)(A + (size_t)(k0 + k) * M + m0 + m4);
            if (SCALEK) { float w = wk[k0 + k]; va.x *= w; va.y *= w; va.z *= w; va.w *= w; }
            *(float4*)&As[k][m4] = va;
        } else {
            int m = tid >> 2, k4 = (tid & 3) << 2;
            float4 va = *(const float4*)(A + (size_t)(m0 + m) * K + k0 + k4);
            As[k4 + 0][m] = va.x; As[k4 + 1][m] = va.y; As[k4 + 2][m] = va.z; As[k4 + 3][m] = va.w;
        }
        if (OPB == 0) {
            int n4 = (tid & 15) << 2, k = tid >> 4;
            *(float4*)&Bs[k][n4] = *(const float4*)(B + (size_t)(k0 + k) * N + n0 + n4);
        } else {
            int n = tid >> 2, k4 = (tid & 3) << 2;
            float4 vb = *(const float4*)(B + (size_t)(n0 + n) * K + k0 + k4);
            Bs[k4 + 0][n] = vb.x; Bs[k4 + 1][n] = vb.y; Bs[k4 + 2][n] = vb.z; Bs[k4 + 3][n] = vb.w;
        }
        __syncthreads();
#pragma unroll
        for (int kk = 0; kk < 16; kk++) {
            float4 a4 = *(const float4*)&As[kk][ty << 2];
            float4 b4 = *(const float4*)&Bs[kk][tx << 2];
            float a[4] = { a4.x, a4.y, a4.z, a4.w };
            float b[4] = { b4.x, b4.y, b4.z, b4.w };
#pragma unroll
            for (int i = 0; i < 4; i++)
#pragma unroll
                for (int j = 0; j < 4; j++) acc[i][j] = fmaf(a[i], b[j], acc[i][j]);
        }
        __syncthreads();
    }

    float* Co = (S > 1) ? (C + (size_t)blockIdx.z * M * N) : C;
    float sc = (S > 1) ? 1.f : alpha;
#pragma unroll
    for (int i = 0; i < 4; i++) {
        float4 o = make_float4(acc[i][0] * sc, acc[i][1] * sc, acc[i][2] * sc, acc[i][3] * sc);
        *(float4*)(Co + (size_t)(m0 + (ty << 2) + i) * N + n0 + (tx << 2)) = o;
    }
}

__global__ void reduce_slabs_k(const float* __restrict__ src, float* __restrict__ dst,
                               int S, int MN, float alpha) {
    int idx = blockIdx.x * blockDim.x + threadIdx.x;
    if (idx >= MN) return;
    float s = 0.f;
    for (int z = 0; z < S; z++) s += src[(size_t)z * MN + idx];
    dst[idx] = s * alpha;
}

// ------------------------------------------------------------------
// sinkhorn (no-max LSE; args bounded) + marginal passes
// ------------------------------------------------------------------
__global__ void sinkrow_k(const float* __restrict__ Mm, const float* __restrict__ v,
                          float* __restrict__ u, int ncols, float log_a) {
    int row = blockIdx.x;
    const float* Mr = Mm + (size_t)row * ncols;
    float s = 0.f;
    for (int j = threadIdx.x; j < ncols; j += blockDim.x) s += fexp(Mr[j] + v[j]);
    s = blockSum(s);
    if (threadIdx.x == 0) u[row] = log_a - logf(s);
}

__global__ void colpartexp_k(const float* __restrict__ Mm, const float* __restrict__ u,
                             float* __restrict__ ps, int ncols, int chunk) {
    int col = blockIdx.x * blockDim.x + threadIdx.x;
    int r0 = blockIdx.y * chunk;
    float s = 0.f;
    for (int r = r0; r < r0 + chunk; r++) s += fexp(Mm[(size_t)r * ncols + col] + u[r]);
    ps[(size_t)blockIdx.y * ncols + col] = s;
}

__global__ void colcombsink_k(const float* __restrict__ ps, float* __restrict__ v,
                              int nch, int ncols, float log_b) {
    int col = blockIdx.x * blockDim.x + threadIdx.x;
    float s = 0.f;
    for (int c = 0; c < nch; c++) s += ps[(size_t)c * ncols + col];
    v[col] = log_b - logf(s);
}

__global__ void colcombmarg_k(const float* __restrict__ ps, const float* __restrict__ v,
                              float* __restrict__ cs, int nch, int ncols) {
    int col = blockIdx.x * blockDim.x + threadIdx.x;
    float s = 0.f;
    for (int c = 0; c < nch; c++) s += ps[(size_t)c * ncols + col];
    cs[col] = s * fexp(v[col]);
}

__global__ void rowsumexp_k(const float* __restrict__ Mm, const float* __restrict__ u,
                            const float* __restrict__ v, float* __restrict__ rs, int ncols) {
    int row = blockIdx.x;
    const float* Mr = Mm + (size_t)row * ncols;
    float s = 0.f;
    for (int j = threadIdx.x; j < ncols; j += blockDim.x) s += fexp(Mr[j] + v[j]);
    s = blockSum(s);
    if (threadIdx.x == 0) rs[row] = s * fexp(u[row]);
}

__global__ void expplan_k(const float* __restrict__ Mm, const float* __restrict__ u,
                          const float* __restrict__ v, float* __restrict__ P) {
    size_t idx = (size_t)blockIdx.x * blockDim.x + threadIdx.x;
    int i = (int)(idx >> 12), j = (int)(idx & 4095);
    P[idx] = fexp(Mm[idx] + u[i] + v[j]);
}

__global__ void rowsumplain_k(const float* __restrict__ P, float* __restrict__ rs, int ncols) {
    int row = blockIdx.x;
    const float* Pr = P + (size_t)row * ncols;
    float s = 0.f;
    for (int j = threadIdx.x; j < ncols; j += blockDim.x) s += Pr[j];
    s = blockSum(s);
    if (threadIdx.x == 0) rs[row] = s;
}

__global__ void colpartplain_k(const float* __restrict__ P, float* __restrict__ ps,
                               int ncols, int chunk) {
    int col = blockIdx.x * blockDim.x + threadIdx.x;
    int r0 = blockIdx.y * chunk;
    float s = 0.f;
    for (int r = r0; r < r0 + chunk; r++) s += P[(size_t)r * ncols + col];
    ps[(size_t)blockIdx.y * ncols + col] = s;
}

__global__ void colcombplain_k(const float* __restrict__ ps, float* __restrict__ cs,
                               int nch, int ncols) {
    int col = blockIdx.x * blockDim.x + threadIdx.x;
    float s = 0.f;
    for (int c = 0; c < nch; c++) s += ps[(size_t)c * ncols + col];
    cs[col] = s;
}

// ------------------------------------------------------------------
// loss passes
// ------------------------------------------------------------------
__global__ void sail_k(const float* __restrict__ Mp, const float* __restrict__ u,
                       const float* __restrict__ v, float* __restrict__ prow,
                       float* __restrict__ dexp, float* __restrict__ dimp) {
    int row = blockIdx.x;
    const float* Mr = Mp + (size_t)row * NP;
    float acc = 0.f;
    for (int j = threadIdx.x; j < NP; j += blockDim.x) {
        float m = Mr[j];
        float z = (j == row) ? (m * 0.5f) : (-m * 0.5f);   // cos*10*target, cos = m/20
        float ls = (z >= 0.f) ? -log1pf(fexp(-z)) : (z - log1pf(fexp(z)));
        acc += ls;
        if (j == row) {
            dexp[row] = (1.f - m * 0.05f) * 0.5f;
            dimp[row] = m + u[row] + v[row];
        }
    }
    acc = blockSum(acc);
    if (threadIdx.x == 0) prow[row] = acc;
}

__global__ void ot_k(const float* __restrict__ Ma, const float* __restrict__ ua,
                     const float* __restrict__ va, const float* __restrict__ Mu,
                     const float* __restrict__ uu, const float* __restrict__ vu,
                     float* __restrict__ prow) {
    int row = blockIdx.x;
    size_t off = (size_t)row * NN;
    float uai = ua[row], uui = uu[row];
    float acc = 0.f;
    for (int j = threadIdx.x; j < NN; j += blockDim.x) {
        float ta = Ma[off + j] + uai + va[j];
        float tu = Mu[off + j] + uui + vu[j];
        acc += fexp(ta) * (ta - tu);
    }
    acc = blockSum(acc);
    if (threadIdx.x == 0) prow[row] = acc;
}

// ------------------------------------------------------------------
// scalar reductions (single block, 1024 threads)
// ------------------------------------------------------------------
__global__ void rsum_k(const float* __restrict__ a, int n, float* __restrict__ dst) {
    float s = 0.f;
    for (int i = threadIdx.x; i < n; i += blockDim.x) s += a[i];
    s = blockSum(s);
    if (threadIdx.x == 0) *dst = s;
}
__global__ void rdot_k(const float* __restrict__ a, const float* __restrict__ b,
                       int n, float* __restrict__ dst) {
    float s = 0.f;
    for (int i = threadIdx.x; i < n; i += blockDim.x) s = fmaf(a[i], b[i], s);
    s = blockSum(s);
    if (threadIdx.x == 0) *dst = s;
}
__global__ void rsqdev_k(const float* __restrict__ a, int n, float c, float* __restrict__ dst) {
    float s = 0.f;
    for (int i = threadIdx.x; i < n; i += blockDim.x) { float d = a[i] - c; s = fmaf(d, d, s); }
    s = blockSum(s);
    if (threadIdx.x == 0) *dst = s;
}

__global__ void final_k(const float* __restrict__ S, float* __restrict__ out) {
    float L_marg = S[0] + S[1] + S[2] + S[3];
    float L_sail = -S[4] / (2048.f * 2048.f);
    float L_exp  = S[5] / 2048.f;
    float L_imp  = -(S[6] / 2048.f + logf(2048.f));
    float L_ot   = S[7];
    float L_div  = (S[8] + S[9] - 2.f * S[10]) / (4096.f * 4096.f);
    float L_gw   = S[11] + S[12] - 2.f * S[13];
    out[0] = L_marg + L_sail + L_exp + L_imp + L_ot + L_div + L_gw;
}

// ------------------------------------------------------------------
// host
// ------------------------------------------------------------------
static float* gp(const void* sym) {
    void* p = nullptr;
    cudaGetSymbolAddress(&p, sym);
    return (float*)p;
}

extern "C" void kernel_launch(void* const* d_in, const int* in_sizes, int n_in,
                              void* d_out, int out_size) {
    (void)in_sizes; (void)n_in; (void)out_size;
    const float* pfXp = (const float*)d_in[0];
    const float* pfYp = (const float*)d_in[1];
    const float* pX   = (const float*)d_in[2];
    const float* pY   = (const float*)d_in[3];
    const float* pfX  = (const float*)d_in[4];
    const float* pfY  = (const float*)d_in[5];
    const float* pXaI = (const float*)d_in[6];
    const float* pYaI = (const float*)d_in[7];

    float *pXa = gp(g_Xa), *pYa = gp(g_Ya);
    float *pSxx = gp(g_Sxx), *pSyy = gp(g_Syy), *pSxy = gp(g_Sxy);
    float *pfXpn = gp(g_fXp), *pfYpn = gp(g_fYp);
    float *pfXn = gp(g_fXn), *pfYn = gp(g_fYn);
    float *pMp = gp(g_Mp), *pMu = gp(g_Mu), *pMa = gp(g_Ma), *pPu = gp(g_Pu);
    float *pXn = gp(g_Xn), *pYn = gp(g_Yn), *pXu = gp(g_Xu), *pYu = gp(g_Yu);
    float *pT1 = gp(g_T1), *pPY = gp(g_PY);
    float *pGxx = gp(g_Gxx), *pGyy = gp(g_Gyy);
    float *pCf = gp(g_Cf), *pDff = gp(g_Dff);
    float *pXF = gp(g_XF), *pFY = gp(g_FY);
    float *pAxx = gp(g_Axx), *pAyy = gp(g_Ayy), *pW = gp(g_W);
    float *pTa = gp(g_Ta), *pTb = gp(g_Tb), *pSlab = gp(g_slab);
    float *puu = gp(g_uu), *pvu = gp(g_vu), *pua = gp(g_ua), *pva = gp(g_va);
    float *pup = gp(g_up), *pvp = gp(g_vp), *pps = gp(g_ps);
    float *pav = gp(g_av), *pbv = gp(g_bv), *prsp = gp(g_rsp), *pcsp = gp(g_csp);
    float *pprow = gp(g_prow), *pdexp = gp(g_dexp), *pdimp = gp(g_dimp), *ppotr = gp(g_potr);
    float *pS = gp(g_S);

    const float logN4 = -logf((float)NN);
    const float logN2 = -logf((float)NP);

    // --- row normalizations ---
    rownorm_k<<<NN, 256>>>(pXaI, pXa, DX);
    rownorm_k<<<NN, 256>>>(pYaI, pYa, DY);
    rownorm_k<<<NP, 256>>>(pfXp, pfXpn, DF);
    rownorm_k<<<NP, 256>>>(pfYp, pfYpn, DF);
    rownorm_k<<<NN, 256>>>(pfX, pfXn, DF);
    rownorm_k<<<NN, 256>>>(pfY, pfYn, DF);
    rownorm_k<<<NN, 256>>>(pX, pXu, DX);
    rownorm_k<<<NN, 256>>>(pY, pYu, DY);

    // --- anchor covariances (TN, split-K slabs) ---
    gemm64<1,0,0><<<dim3(DX/64, DX/64, SPLITK), 256>>>(pXa, pXa, pSlab, DX, DX, NN, 1.f, nullptr);
    reduce_slabs_k<<<(DX*DX+255)/256, 256>>>(pSlab, pSxx, SPLITK, DX*DX, 1.f/NN);
    gemm64<1,0,0><<<dim3(DY/64, DY/64, SPLITK), 256>>>(pYa, pYa, pSlab, DY, DY, NN, 1.f, nullptr);
    reduce_slabs_k<<<(DY*DY+255)/256, 256>>>(pSlab, pSyy, SPLITK, DY*DY, 1.f/NN);
    gemm64<1,0,0><<<dim3(DY/64, DX/64, SPLITK), 256>>>(pXa, pYa, pSlab, DX, DY, NN, 1.f, nullptr);
    reduce_slabs_k<<<(DX*DY+255)/256, 256>>>(pSlab, pSxy, SPLITK, DX*DY, 1.f/NN);

    // --- anchored normalizations Xn, Yn ---
    gemm64<0,0,0><<<dim3(DX/64, NN/64), 256>>>(pX, pSxx, pT1, NN, DX, DX, 1.f, nullptr);
    rowdot_scale_k<<<NN, 256>>>(pX, pT1, pXn, DX);
    gemm64<0,0,0><<<dim3(DY/64, NN/64), 256>>>(pY, pSyy, pT1, NN, DY, DY, 1.f, nullptr);
    rowdot_scale_k<<<NN, 256>>>(pY, pT1, pYn, DY);

    // --- cost matrices (M = sim * 20) ---
    gemm64<0,0,0><<<dim3(DY/64, NN/64), 256>>>(pXn, pSxy, pT1, NN, DY, DX, 1.f, nullptr);
    gemm64<0,1,0><<<dim3(NN/64, NN/64), 256>>>(pT1, pYn, pMa, NN, NN, DY, 20.f, nullptr);
    gemm64<0,1,0><<<dim3(NN/64, NN/64), 256>>>(pfXn, pfYn, pMu, NN, NN, DF, 20.f, nullptr);
    gemm64<0,1,0><<<dim3(NP/64, NP/64), 256>>>(pfXpn, pfYpn, pMp, NP, NP, DF, 20.f, nullptr);

    // --- sinkhorn: plan_u on Mu ---
    cudaMemsetAsync(puu, 0, NN*sizeof(float));
    cudaMemsetAsync(pvu, 0, NN*sizeof(float));
    for (int it = 0; it < 10; ++it) {
        sinkrow_k<<<NN, 256>>>(pMu, pvu, puu, NN, logN4);
        colpartexp_k<<<dim3(NN/256, 32), 256>>>(pMu, puu, pps, NN, 128);
        colcombsink_k<<<NN/256, 256>>>(pps, pvu, 32, NN, logN4);
    }
    // --- sinkhorn: plan_a on Ma ---
    cudaMemsetAsync(pua, 0, NN*sizeof(float));
    cudaMemsetAsync(pva, 0, NN*sizeof(float));
    for (int it = 0; it < 10; ++it) {
        sinkrow_k<<<NN, 256>>>(pMa, pva, pua, NN, logN4);
        colpartexp_k<<<dim3(NN/256, 32), 256>>>(pMa, pua, pps, NN, 128);
        colcombsink_k<<<NN/256, 256>>>(pps, pva, 32, NN, logN4);
    }
    // --- sinkhorn: plan_p on Mp ---
    cudaMemsetAsync(pup, 0, NP*sizeof(float));
    cudaMemsetAsync(pvp, 0, NP*sizeof(float));
    for (int it = 0; it < 10; ++it) {
        sinkrow_k<<<NP, 256>>>(pMp, pvp, pup, NP, logN2);
        colpartexp_k<<<dim3(NP/256, 16), 256>>>(pMp, pup, pps, NP, 128);
        colcombsink_k<<<NP/256, 256>>>(pps, pvp, 16, NP, logN2);
    }

    // --- plan_u materialize + marginals a, b ---
    expplan_k<<<(unsigned)((size_t)NN*NN/1024), 1024>>>(pMu, puu, pvu, pPu);
    rowsumplain_k<<<NN, 256>>>(pPu, pav, NN);
    colpartplain_k<<<dim3(NN/256, 32), 256>>>(pPu, pps, NN, 128);
    colcombplain_k<<<NN/256, 256>>>(pps, pbv, 32, NN);
    rsqdev_k<<<1, 1024>>>(pav, NN, 1.f/NN, pS + 2);
    rsqdev_k<<<1, 1024>>>(pbv, NN, 1.f/NN, pS + 3);

    // --- plan_p marginals ---
    rowsumexp_k<<<NP, 256>>>(pMp, pup, pvp, prsp, NP);
    colpartexp_k<<<dim3(NP/256, 16), 256>>>(pMp, pup, pps, NP, 128);
    colcombmarg_k<<<NP/256, 256>>>(pps, pvp, pcsp, 16, NP);
    rsqdev_k<<<1, 1024>>>(prsp, NP, 1.f/NP, pS + 0);
    rsqdev_k<<<1, 1024>>>(pcsp, NP, 1.f/NP, pS + 1);

    // --- sail / exp / imp ---
    sail_k<<<NP, 256>>>(pMp, pup, pvp, pprow, pdexp, pdimp);
    rsum_k<<<1, 1024>>>(pprow, NP, pS + 4);
    rsum_k<<<1, 1024>>>(pdexp, NP, pS + 5);
    rsum_k<<<1, 1024>>>(pdimp, NP, pS + 6);

    // --- OT KL term ---
    ot_k<<<NN, 256>>>(pMa, pua, pva, pMu, puu, pvu, ppotr);
    rsum_k<<<1, 1024>>>(ppotr, NN, pS + 7);

    // --- divergence terms ---
    gemm64<1,0,0><<<dim3(DX/64, DX/64, SPLITK), 256>>>(pXn, pXn, pSlab, DX, DX, NN, 1.f, nullptr);
    reduce_slabs_k<<<(DX*DX+255)/256, 256>>>(pSlab, pGxx, SPLITK, DX*DX, 1.f);
    gemm64<1,0,0><<<dim3(DY/64, DY/64, SPLITK), 256>>>(pYn, pYn, pSlab, DY, DY, NN, 1.f, nullptr);
    reduce_slabs_k<<<(DY*DY+255)/256, 256>>>(pSlab, pGyy, SPLITK, DY*DY, 1.f);
    gemm64<1,0,0><<<dim3(DF/64, DF/64, SPLITK), 256>>>(pfXn, pfXn, pSlab, DF, DF, NN, 1.f, nullptr);
    reduce_slabs_k<<<(DF*DF+255)/256, 256>>>(pSlab, pCf, SPLITK, DF*DF, 1.f);
    gemm64<1,0,0><<<dim3(DF/64, DF/64, SPLITK), 256>>>(pfYn, pfYn, pSlab, DF, DF, NN, 1.f, nullptr);
    reduce_slabs_k<<<(DF*DF+255)/256, 256>>>(pSlab, pDff, SPLITK, DF*DF, 1.f);
    gemm64<1,0,0><<<dim3(DF/64, DX/64, SPLITK), 256>>>(pXn, pfXn, pSlab, DX, DF, NN, 1.f, nullptr);
    reduce_slabs_k<<<(DX*DF+255)/256, 256>>>(pSlab, pXF, SPLITK, DX*DF, 1.f);
    gemm64<1,0,0><<<dim3(DY/64, DF/64, SPLITK), 256>>>(pfYn, pYn, pSlab, DF, DY, NN, 1.f, nullptr);
    reduce_slabs_k<<<(DF*DY+255)/256, 256>>>(pSlab, pFY, SPLITK, DF*DY, 1.f);

    gemm64<0,0,0><<<dim3(DY/64, DX/64), 256>>>(pGxx, pSxy, pTa, DX, DY, DX, 1.f, nullptr);
    gemm64<0,0,0><<<dim3(DY/64, DX/64), 256>>>(pTa, pGyy, pTb, DX, DY, DY, 1.f, nullptr);
    rdot_k<<<1, 1024>>>(pTb, pSxy, DX*DY, pS + 8);
    rdot_k<<<1, 1024>>>(pCf, pDff, DF*DF, pS + 9);
    gemm64<0,0,0><<<dim3(DY/64, DX/64), 256>>>(pXF, pFY, pTa, DX, DY, DF, 1.f, nullptr);
    rdot_k<<<1, 1024>>>(pTa, pSxy, DX*DY, pS + 10);

    // --- GW terms ---
    gemm64<1,0,1><<<dim3(DX/64, DX/64, SPLITK), 256>>>(pXu, pXu, pSlab, DX, DX, NN, 1.f, pav);
    reduce_slabs_k<<<(DX*DX+255)/256, 256>>>(pSlab, pAxx, SPLITK, DX*DX, 1.f);
    gemm64<1,0,1><<<dim3(DY/64, DY/64, SPLITK), 256>>>(pYu, pYu, pSlab, DY, DY, NN, 1.f, pbv);
    reduce_slabs_k<<<(DY*DY+255)/256, 256>>>(pSlab, pAyy, SPLITK, DY*DY, 1.f);
    rdot_k<<<1, 1024>>>(pAxx, pAxx, DX*DX, pS + 11);
    rdot_k<<<1, 1024>>>(pAyy, pAyy, DY*DY, pS + 12);

    gemm64<0,0,0><<<dim3(DY/64, NN/64), 256>>>(pPu, pYu, pPY, NN, DY, NN, 1.f, nullptr);
    gemm64<1,0,0><<<dim3(DY/64, DX/64, SPLITK), 256>>>(pXu, pPY, pSlab, DX, DY, NN, 1.f, nullptr);
    reduce_slabs_k<<<(DX*DY+255)/256, 256>>>(pSlab, pW, SPLITK, DX*DY, 1.f);
    rdot_k<<<1, 1024>>>(pW, pW, DX*DY, pS + 13);

    // --- combine ---
    final_k<<<1, 1>>>(pS, (float*)d_out);
}